// round 2
// baseline (speedup 1.0000x reference)
#include <cuda_runtime.h>

#define DM 2048   // D_MODEL
#define DF 8192   // D_FF
#define RK 32     // RANK
#define SL 512    // S (B=1, H=1)

// Scratch for intermediate mlp = silu(gate_out) * up_out  : [DF, SL] fp32 = 16 MB
__device__ float g_mlp[DF * SL];

// ---------------------------------------------------------------------------
// Kernel 1: gate & up projections (fused dequant) + SwiGLU epilogue.
//   gate_out[f,s] = sum_c Gs[f,c] * (GA[f,:]@GB[:,c]) * x[c,s]   (same for up)
//   mlp[f,s] = silu(gate_out) * up_out
// Tiles: BM=64 (f), BN=128 (s), BK=16 (c). 256 threads, micro-tile 4x8 per matrix.
// ---------------------------------------------------------------------------
__global__ __launch_bounds__(256, 1) void k_gateup(
    const float* __restrict__ x,
    const float* __restrict__ Gs, const float* __restrict__ GA, const float* __restrict__ GB,
    const float* __restrict__ Us, const float* __restrict__ UA, const float* __restrict__ UB)
{
    const int BM = 64, BN = 128, BK = 16;

    __shared__ float sAg[64][RK];     // gate_scale_A rows for this f-tile
    __shared__ float sAu[64][RK];
    __shared__ float sBg[RK][BK];     // gate_scale_B chunk
    __shared__ float sBu[RK][BK];
    __shared__ float swg[64][BK];     // dequantized gate weight tile
    __shared__ float swu[64][BK];
    __shared__ float sx[BK][BN];      // x tile

    const int tid   = threadIdx.x;
    const int fbase = blockIdx.x * BM;
    const int sbase = blockIdx.y * BN;
    const int tx = tid & 15;          // col group
    const int ty = tid >> 4;          // row group
    const int row0 = ty;              // dequant rows: row0 + 16*t
    const int dcol = tx;              // dequant col

    // Load scale_A slices once (fully coalesced).
    #pragma unroll
    for (int t = 0; t < 8; t++) {
        int idx = tid + t * 256;          // 0..2047
        int row = idx >> 5, r = idx & 31;
        sAg[row][r] = GA[(fbase + row) * RK + r];
        sAu[row][r] = UA[(fbase + row) * RK + r];
    }

    float accg[4][8], accu[4][8];
    #pragma unroll
    for (int i = 0; i < 4; i++)
        #pragma unroll
        for (int j = 0; j < 8; j++) { accg[i][j] = 0.f; accu[i][j] = 0.f; }

    for (int c0 = 0; c0 < DM; c0 += BK) {
        __syncthreads();   // previous iteration's reads of shared are done

        // scale_B chunks: 32x16 each, 2 elems/thread
        {
            int idx = tid;
            #pragma unroll
            for (int t = 0; t < 2; t++) {
                int r = idx >> 4, c = idx & 15;
                sBg[r][c] = GB[r * DM + c0 + c];
                sBu[r][c] = UB[r * DM + c0 + c];
                idx += 256;
            }
        }
        // x tile: 16x128, 8 elems/thread, coalesced
        #pragma unroll
        for (int t = 0; t < 8; t++) {
            int idx = tid + t * 256;
            int r = idx >> 7, c = idx & 127;
            sx[r][c] = x[(c0 + r) * SL + sbase + c];
        }
        // snapped weights into registers (mapping matches dequant mapping below)
        float rg[4], ru[4];
        #pragma unroll
        for (int t = 0; t < 4; t++) {
            int idx = tid + t * 256;
            int row = idx >> 4, c = idx & 15;   // row = row0+16t, c = dcol
            rg[t] = Gs[(fbase + row) * DM + c0 + c];
            ru[t] = Us[(fbase + row) * DM + c0 + c];
        }
        __syncthreads();   // sB, sx ready

        // Dequant: scale[row,col] = A[row,:]@B[:,col]; thread owns 4 rows x 1 col.
        float dg[4] = {0.f, 0.f, 0.f, 0.f};
        float du[4] = {0.f, 0.f, 0.f, 0.f};
        #pragma unroll
        for (int r4 = 0; r4 < RK; r4 += 4) {
            float4 ag0 = *(const float4*)&sAg[row0     ][r4];
            float4 ag1 = *(const float4*)&sAg[row0 + 16][r4];
            float4 ag2 = *(const float4*)&sAg[row0 + 32][r4];
            float4 ag3 = *(const float4*)&sAg[row0 + 48][r4];
            float4 au0 = *(const float4*)&sAu[row0     ][r4];
            float4 au1 = *(const float4*)&sAu[row0 + 16][r4];
            float4 au2 = *(const float4*)&sAu[row0 + 32][r4];
            float4 au3 = *(const float4*)&sAu[row0 + 48][r4];
            float bg0 = sBg[r4 + 0][dcol], bg1 = sBg[r4 + 1][dcol];
            float bg2 = sBg[r4 + 2][dcol], bg3 = sBg[r4 + 3][dcol];
            float bu0 = sBu[r4 + 0][dcol], bu1 = sBu[r4 + 1][dcol];
            float bu2 = sBu[r4 + 2][dcol], bu3 = sBu[r4 + 3][dcol];
            dg[0] += ag0.x*bg0 + ag0.y*bg1 + ag0.z*bg2 + ag0.w*bg3;
            dg[1] += ag1.x*bg0 + ag1.y*bg1 + ag1.z*bg2 + ag1.w*bg3;
            dg[2] += ag2.x*bg0 + ag2.y*bg1 + ag2.z*bg2 + ag2.w*bg3;
            dg[3] += ag3.x*bg0 + ag3.y*bg1 + ag3.z*bg2 + ag3.w*bg3;
            du[0] += au0.x*bu0 + au0.y*bu1 + au0.z*bu2 + au0.w*bu3;
            du[1] += au1.x*bu0 + au1.y*bu1 + au1.z*bu2 + au1.w*bu3;
            du[2] += au2.x*bu0 + au2.y*bu1 + au2.z*bu2 + au2.w*bu3;
            du[3] += au3.x*bu0 + au3.y*bu1 + au3.z*bu2 + au3.w*bu3;
        }
        #pragma unroll
        for (int t = 0; t < 4; t++) {
            int row = row0 + 16 * t;
            swg[row][dcol] = rg[t] * dg[t];
            swu[row][dcol] = ru[t] * du[t];
        }
        __syncthreads();   // dequant tiles ready

        // Main GEMM micro-kernel
        #pragma unroll
        for (int k = 0; k < BK; k++) {
            float xv[8];
            #pragma unroll
            for (int j = 0; j < 8; j++) xv[j] = sx[k][tx + 16 * j];
            #pragma unroll
            for (int i = 0; i < 4; i++) {
                float wg = swg[ty + 16 * i][k];
                float wu = swu[ty + 16 * i][k];
                #pragma unroll
                for (int j = 0; j < 8; j++) {
                    accg[i][j] += wg * xv[j];
                    accu[i][j] += wu * xv[j];
                }
            }
        }
    }

    // Epilogue: SwiGLU, write to scratch
    #pragma unroll
    for (int i = 0; i < 4; i++) {
        int f = fbase + ty + 16 * i;
        #pragma unroll
        for (int j = 0; j < 8; j++) {
            int s = sbase + tx + 16 * j;
            float g = accg[i][j];
            float u = accu[i][j];
            float m = (g / (1.f + __expf(-g))) * u;   // silu(g) * u
            g_mlp[f * SL + s] = m;
        }
    }
}

// ---------------------------------------------------------------------------
// Kernel 2: down projection (fused dequant).
//   out[m,s] = sum_ff Ds[m,ff] * (DA[m,:]@DB[:,ff]) * mlp[ff,s]
// Tiles: BM=32, BN=128, BK=16. 256 threads, micro-tile 2x8.
// ---------------------------------------------------------------------------
__global__ __launch_bounds__(256, 1) void k_down(
    const float* __restrict__ Ds, const float* __restrict__ DA,
    const float* __restrict__ DB, float* __restrict__ out)
{
    const int BM = 32, BN = 128, BK = 16;

    __shared__ float sAd[32][RK];
    __shared__ float sBd[RK][BK];
    __shared__ float swd[32][BK];
    __shared__ float sx[BK][BN];

    const int tid   = threadIdx.x;
    const int mbase = blockIdx.x * BM;
    const int sbase = blockIdx.y * BN;
    const int tx = tid & 15;
    const int ty = tid >> 4;
    const int row0 = ty;
    const int dcol = tx;

    // scale_A rows: 32x32 = 1024 elems, 4/thread
    #pragma unroll
    for (int t = 0; t < 4; t++) {
        int idx = tid + t * 256;
        int row = idx >> 5, r = idx & 31;
        sAd[row][r] = DA[(mbase + row) * RK + r];
    }

    float acc[2][8];
    #pragma unroll
    for (int i = 0; i < 2; i++)
        #pragma unroll
        for (int j = 0; j < 8; j++) acc[i][j] = 0.f;

    for (int c0 = 0; c0 < DF; c0 += BK) {
        __syncthreads();

        // scale_B chunk: 32x16, 2/thread
        {
            int idx = tid;
            #pragma unroll
            for (int t = 0; t < 2; t++) {
                int r = idx >> 4, c = idx & 15;
                sBd[r][c] = DB[r * DF + c0 + c];
                idx += 256;
            }
        }
        // mlp tile: 16x128, 8/thread
        #pragma unroll
        for (int t = 0; t < 8; t++) {
            int idx = tid + t * 256;
            int r = idx >> 7, c = idx & 127;
            sx[r][c] = g_mlp[(c0 + r) * SL + sbase + c];
        }
        // snapped: 32x16 = 512 elems, 2/thread (rows row0, row0+16; col dcol)
        float rs[2];
        #pragma unroll
        for (int t = 0; t < 2; t++) {
            int idx = tid + t * 256;
            int row = idx >> 4, c = idx & 15;
            rs[t] = Ds[(mbase + row) * DF + c0 + c];
        }
        __syncthreads();

        // Dequant: 2 rows x 1 col per thread
        float dd[2] = {0.f, 0.f};
        #pragma unroll
        for (int r4 = 0; r4 < RK; r4 += 4) {
            float4 a0 = *(const float4*)&sAd[row0     ][r4];
            float4 a1 = *(const float4*)&sAd[row0 + 16][r4];
            float b0 = sBd[r4 + 0][dcol], b1 = sBd[r4 + 1][dcol];
            float b2 = sBd[r4 + 2][dcol], b3 = sBd[r4 + 3][dcol];
            dd[0] += a0.x*b0 + a0.y*b1 + a0.z*b2 + a0.w*b3;
            dd[1] += a1.x*b0 + a1.y*b1 + a1.z*b2 + a1.w*b3;
        }
        swd[row0     ][dcol] = rs[0] * dd[0];
        swd[row0 + 16][dcol] = rs[1] * dd[1];
        __syncthreads();

        // Main GEMM micro-kernel
        #pragma unroll
        for (int k = 0; k < BK; k++) {
            float xv[8];
            #pragma unroll
            for (int j = 0; j < 8; j++) xv[j] = sx[k][tx + 16 * j];
            #pragma unroll
            for (int i = 0; i < 2; i++) {
                float wd = swd[ty + 16 * i][k];
                #pragma unroll
                for (int j = 0; j < 8; j++) acc[i][j] += wd * xv[j];
            }
        }
    }

    #pragma unroll
    for (int i = 0; i < 2; i++) {
        int m = mbase + ty + 16 * i;
        #pragma unroll
        for (int j = 0; j < 8; j++) {
            int s = sbase + tx + 16 * j;
            out[m * SL + s] = acc[i][j];
        }
    }
}

// ---------------------------------------------------------------------------
extern "C" void kernel_launch(void* const* d_in, const int* in_sizes, int n_in,
                              void* d_out, int out_size)
{
    (void)in_sizes; (void)n_in; (void)out_size;
    const float* x  = (const float*)d_in[0];
    const float* Gs = (const float*)d_in[1];
    const float* GA = (const float*)d_in[2];
    const float* GB = (const float*)d_in[3];
    const float* Us = (const float*)d_in[4];
    const float* UA = (const float*)d_in[5];
    const float* UB = (const float*)d_in[6];
    const float* Ds = (const float*)d_in[7];
    const float* DA = (const float*)d_in[8];
    const float* DB = (const float*)d_in[9];
    float* out = (float*)d_out;

    dim3 g1(DF / 64, SL / 128);   // 128 x 4 = 512 blocks
    k_gateup<<<g1, 256>>>(x, Gs, GA, GB, Us, UA, UB);

    dim3 g2(DM / 32, SL / 128);   // 64 x 4 = 256 blocks
    k_down<<<g2, 256>>>(Ds, DA, DB, out);
}

// round 4
// speedup vs baseline: 5.4779x; 5.4779x over previous
#include <cuda_runtime.h>
#include <cstdint>

#define DM 2048   // D_MODEL
#define DF 8192   // D_FF
#define RK 32     // RANK
#define SL 512    // S

// ---------------------------------------------------------------------------
// Global scratch
// ---------------------------------------------------------------------------
__device__ float g_Wg[DF * DM];       // gate_eff, tf32-rounded
__device__ float g_Wu[DF * DM];       // up_eff
__device__ float g_Wd[DM * DF];       // down_eff
__device__ float g_xT[SL * DM];       // x transposed [s][c], tf32-rounded
__device__ float g_mlpT[SL * DF];     // silu(g)*u transposed [s][ff], tf32-rounded
__device__ float g_part[4 * DM * SL]; // split-K partials for down

// ---------------------------------------------------------------------------
// Helpers
// ---------------------------------------------------------------------------
__device__ __forceinline__ float to_tf32(float x) {
    uint32_t u;
    asm("cvt.rna.tf32.f32 %0, %1;" : "=r"(u) : "f"(x));
    return __uint_as_float(u);
}
__device__ __forceinline__ uint32_t smem_u32(const void* p) {
    uint32_t a;
    asm("{ .reg .u64 t; cvta.to.shared.u64 t, %1; cvt.u32.u64 %0, t; }" : "=r"(a) : "l"(p));
    return a;
}
__device__ __forceinline__ void cp16(uint32_t dst, const void* src) {
    asm volatile("cp.async.cg.shared.global [%0], [%1], 16;" :: "r"(dst), "l"(src));
}
__device__ __forceinline__ void cp_commit() { asm volatile("cp.async.commit_group;"); }
__device__ __forceinline__ void cp_wait1()  { asm volatile("cp.async.wait_group 1;" ::: "memory"); }
__device__ __forceinline__ void cp_wait0()  { asm volatile("cp.async.wait_group 0;" ::: "memory"); }

// m16n8k8 tf32 MMA (row.col, fp32 accum). a: 4 regs, b: 2 regs, c: 4 fp32.
__device__ __forceinline__ void mma8(float* c, const float* a, const float* b) {
    asm volatile(
        "mma.sync.aligned.m16n8k8.row.col.f32.tf32.tf32.f32 "
        "{%0,%1,%2,%3}, {%4,%5,%6,%7}, {%8,%9}, {%0,%1,%2,%3};"
        : "+f"(c[0]), "+f"(c[1]), "+f"(c[2]), "+f"(c[3])
        : "r"(__float_as_uint(a[0])), "r"(__float_as_uint(a[1])),
          "r"(__float_as_uint(a[2])), "r"(__float_as_uint(a[3])),
          "r"(__float_as_uint(b[0])), "r"(__float_as_uint(b[1])));
}

#define PADK 36                  // 32 k-floats padded to 36 (16B-aligned, conflict-free)
#define TILE_F (128 * PADK * 4)  // bytes per 128-row tile stage: 18432

// ---------------------------------------------------------------------------
// Kernel 1: dequant  W' = rna_tf32( Ws .* (A @ B) ).  Tile: 32 rows x 128 cols.
// ---------------------------------------------------------------------------
__global__ __launch_bounds__(256, 2) void k_dequant(
    const float* __restrict__ Ws, const float* __restrict__ Aa,
    const float* __restrict__ Bb, float* __restrict__ Wo, int cols)
{
    __shared__ float sA[32][33];
    __shared__ float sB[32][128];
    int tid = threadIdx.x, tx = tid & 31, ty = tid >> 5;
    int cb = blockIdx.x * 128, fb = blockIdx.y * 32;

    #pragma unroll
    for (int t = 0; t < 4; t++) {
        int idx = tid + t * 256;
        sA[idx >> 5][idx & 31] = Aa[(fb + (idx >> 5)) * RK + (idx & 31)];
    }
    #pragma unroll
    for (int t = 0; t < 16; t++) {
        int idx = tid + t * 256;
        sB[idx >> 7][idx & 127] = Bb[(idx >> 7) * cols + cb + (idx & 127)];
    }
    __syncthreads();

    float acc[4][4];
    #pragma unroll
    for (int i = 0; i < 4; i++)
        #pragma unroll
        for (int j = 0; j < 4; j++) acc[i][j] = 0.f;

    #pragma unroll 8
    for (int r = 0; r < RK; r++) {
        float4 b = *(const float4*)&sB[r][tx * 4];
        #pragma unroll
        for (int i = 0; i < 4; i++) {
            float a = sA[ty * 4 + i][r];
            acc[i][0] += a * b.x; acc[i][1] += a * b.y;
            acc[i][2] += a * b.z; acc[i][3] += a * b.w;
        }
    }
    #pragma unroll
    for (int i = 0; i < 4; i++) {
        int f = fb + ty * 4 + i;
        const float4 w = *(const float4*)&Ws[f * cols + cb + tx * 4];
        float4 o;
        o.x = to_tf32(w.x * acc[i][0]); o.y = to_tf32(w.y * acc[i][1]);
        o.z = to_tf32(w.z * acc[i][2]); o.w = to_tf32(w.w * acc[i][3]);
        *(float4*)&Wo[f * cols + cb + tx * 4] = o;
    }
}

// ---------------------------------------------------------------------------
// x transpose + tf32 round
// ---------------------------------------------------------------------------
__global__ __launch_bounds__(256, 4) void k_xt(const float* __restrict__ x)
{
    __shared__ float sm[32][33];
    int tid = threadIdx.x, tx = tid & 31, ty = tid >> 5;
    int cb = blockIdx.x * 32, sb = blockIdx.y * 32;
    #pragma unroll
    for (int i = 0; i < 4; i++)
        sm[ty + i * 8][tx] = x[(cb + ty + i * 8) * SL + sb + tx];
    __syncthreads();
    #pragma unroll
    for (int i = 0; i < 4; i++)
        g_xT[(sb + ty + i * 8) * DM + cb + tx] = to_tf32(sm[tx][ty + i * 8]);
}

// ---------------------------------------------------------------------------
// Stage loader: 128 rows x 32 k-floats, SW-free padded layout [row][PADK]
// ---------------------------------------------------------------------------
__device__ __forceinline__ void load_tile(uint32_t dst, const float* __restrict__ src,
                                          int row_base, int ld, int c0, int tid)
{
    #pragma unroll
    for (int t = 0; t < 4; t++) {
        int id = tid + t * 256;
        int r = id >> 3, cbk = id & 7;
        cp16(dst + (r * PADK + cbk * 4) * 4, src + (row_base + r) * ld + c0 + cbk * 4);
    }
}

// ---------------------------------------------------------------------------
// Kernel 2: gate+up tf32 GEMM (mma.sync) + SwiGLU -> g_mlpT
// CTA: 128 f x 128 s, BK=32, 8 warps (warp_m 0..3 x warp_n 0..1, each 32x64).
// SMEM/stage: Ag | Au | Bx  (3 x 18432 B), double-buffered = 110592 B.
// ---------------------------------------------------------------------------
#define K2_STG (3 * TILE_F)
#define K2_SMEM (2 * K2_STG)

__global__ __launch_bounds__(256, 1) void k_gemm_gateup()
{
    extern __shared__ float smem[];
    const uint32_t su = smem_u32(smem);
    const int tid = threadIdx.x, wid = tid >> 5, lane = tid & 31;
    const int g = lane >> 2, tg = lane & 3;
    const int warp_m = wid & 3, warp_n = wid >> 2;
    const int fbase = blockIdx.x * 128, sb = blockIdx.y * 128;

    float accg[2][8][4], accu[2][8][4];
    #pragma unroll
    for (int mt = 0; mt < 2; mt++)
        #pragma unroll
        for (int nt = 0; nt < 8; nt++)
            #pragma unroll
            for (int i = 0; i < 4; i++) { accg[mt][nt][i] = 0.f; accu[mt][nt][i] = 0.f; }

    const int SF = K2_STG / 4;  // stage stride in floats

    // prologue: stage 0
    load_tile(su,                 g_Wg, fbase, DM, 0, tid);
    load_tile(su + TILE_F,        g_Wu, fbase, DM, 0, tid);
    load_tile(su + 2 * TILE_F,    g_xT, sb,    DM, 0, tid);
    cp_commit();

    for (int i = 0; i < 64; i++) {
        if (i < 63) {
            uint32_t b = su + ((i + 1) & 1) * K2_STG;
            int c0 = (i + 1) * 32;
            load_tile(b,              g_Wg, fbase, DM, c0, tid);
            load_tile(b + TILE_F,     g_Wu, fbase, DM, c0, tid);
            load_tile(b + 2 * TILE_F, g_xT, sb,    DM, c0, tid);
            cp_commit();
            cp_wait1();
        } else {
            cp_wait0();
        }
        __syncthreads();

        const float* Ag = smem + (i & 1) * SF;
        const float* Au = Ag + TILE_F / 4;
        const float* Bx = Ag + 2 * TILE_F / 4;

        #pragma unroll
        for (int ks = 0; ks < 4; ks++) {
            const int k0 = ks * 8;
            float bq[8][2];
            #pragma unroll
            for (int nt = 0; nt < 8; nt++) {
                const float* bp = Bx + (warp_n * 64 + nt * 8 + g) * PADK + k0 + tg;
                bq[nt][0] = bp[0]; bq[nt][1] = bp[4];
            }
            #pragma unroll
            for (int mt = 0; mt < 2; mt++) {
                const float* agp = Ag + (warp_m * 32 + mt * 16 + g) * PADK + k0 + tg;
                const float* aup = Au + (warp_m * 32 + mt * 16 + g) * PADK + k0 + tg;
                float ag[4], au[4];
                ag[0] = agp[0]; ag[1] = agp[8 * PADK]; ag[2] = agp[4]; ag[3] = agp[8 * PADK + 4];
                au[0] = aup[0]; au[1] = aup[8 * PADK]; au[2] = aup[4]; au[3] = aup[8 * PADK + 4];
                #pragma unroll
                for (int nt = 0; nt < 8; nt++) {
                    mma8(accg[mt][nt], ag, bq[nt]);
                    mma8(accu[mt][nt], au, bq[nt]);
                }
            }
        }
        __syncthreads();
    }

    // epilogue: SwiGLU, smem transpose [s][f], coalesced write to g_mlpT
    float* so = smem;  // stride 132, 128*132*4 = 67584 B < K2_SMEM
    #pragma unroll
    for (int mt = 0; mt < 2; mt++)
        #pragma unroll
        for (int nt = 0; nt < 8; nt++) {
            int r0 = warp_m * 32 + mt * 16 + g;
            int c0 = warp_n * 64 + nt * 8 + 2 * tg;
            #pragma unroll
            for (int i = 0; i < 4; i++) {
                int r = r0 + (i >> 1) * 8, c = c0 + (i & 1);
                float gg = accg[mt][nt][i], uu = accu[mt][nt][i];
                so[c * 132 + r] = (gg / (1.f + __expf(-gg))) * uu;
            }
        }
    __syncthreads();
    #pragma unroll
    for (int t = 0; t < 64; t++) {
        int idx = tid + t * 256;
        int s = idx >> 7, f = idx & 127;
        g_mlpT[(sb + s) * DF + fbase + f] = to_tf32(so[s * 132 + f]);
    }
}

// ---------------------------------------------------------------------------
// Kernel 3: down tf32 GEMM, split-K=4.  CTA: 128 m x 128 s, K-slice 2048.
// SMEM/stage: Ad | Bm (2 x 18432 B), double-buffered = 73728 B.
// ---------------------------------------------------------------------------
#define K3_STG (2 * TILE_F)
#define K3_SMEM (2 * K3_STG)

__global__ __launch_bounds__(256, 1) void k_gemm_down()
{
    extern __shared__ float smem[];
    const uint32_t su = smem_u32(smem);
    const int tid = threadIdx.x, wid = tid >> 5, lane = tid & 31;
    const int g = lane >> 2, tg = lane & 3;
    const int warp_m = wid & 3, warp_n = wid >> 2;
    const int mbase = blockIdx.x * 128, sb = blockIdx.y * 128;
    const int kbase = blockIdx.z * 2048;

    float acc[2][8][4];
    #pragma unroll
    for (int mt = 0; mt < 2; mt++)
        #pragma unroll
        for (int nt = 0; nt < 8; nt++)
            #pragma unroll
            for (int i = 0; i < 4; i++) acc[mt][nt][i] = 0.f;

    const int SF = K3_STG / 4;

    load_tile(su,          g_Wd,   mbase, DF, kbase, tid);
    load_tile(su + TILE_F, g_mlpT, sb,    DF, kbase, tid);
    cp_commit();

    for (int i = 0; i < 64; i++) {
        if (i < 63) {
            uint32_t b = su + ((i + 1) & 1) * K3_STG;
            int c0 = kbase + (i + 1) * 32;
            load_tile(b,          g_Wd,   mbase, DF, c0, tid);
            load_tile(b + TILE_F, g_mlpT, sb,    DF, c0, tid);
            cp_commit();
            cp_wait1();
        } else {
            cp_wait0();
        }
        __syncthreads();

        const float* Ad = smem + (i & 1) * SF;
        const float* Bm = Ad + TILE_F / 4;

        #pragma unroll
        for (int ks = 0; ks < 4; ks++) {
            const int k0 = ks * 8;
            float bq[8][2];
            #pragma unroll
            for (int nt = 0; nt < 8; nt++) {
                const float* bp = Bm + (warp_n * 64 + nt * 8 + g) * PADK + k0 + tg;
                bq[nt][0] = bp[0]; bq[nt][1] = bp[4];
            }
            #pragma unroll
            for (int mt = 0; mt < 2; mt++) {
                const float* ap = Ad + (warp_m * 32 + mt * 16 + g) * PADK + k0 + tg;
                float a[4];
                a[0] = ap[0]; a[1] = ap[8 * PADK]; a[2] = ap[4]; a[3] = ap[8 * PADK + 4];
                #pragma unroll
                for (int nt = 0; nt < 8; nt++) mma8(acc[mt][nt], a, bq[nt]);
            }
        }
        __syncthreads();
    }

    // epilogue: smem stage [m][s], coalesced partial writes
    float* so = smem;  // stride 132
    #pragma unroll
    for (int mt = 0; mt < 2; mt++)
        #pragma unroll
        for (int nt = 0; nt < 8; nt++) {
            int r0 = warp_m * 32 + mt * 16 + g;
            int c0 = warp_n * 64 + nt * 8 + 2 * tg;
            #pragma unroll
            for (int i = 0; i < 4; i++) {
                int r = r0 + (i >> 1) * 8, c = c0 + (i & 1);
                so[r * 132 + c] = acc[mt][nt][i];
            }
        }
    __syncthreads();
    #pragma unroll
    for (int t = 0; t < 64; t++) {
        int idx = tid + t * 256;
        int m = idx >> 7, s = idx & 127;
        g_part[(blockIdx.z * DM + mbase + m) * SL + sb + s] = so[m * 132 + s];
    }
}

// ---------------------------------------------------------------------------
// Kernel 4: split-K reduce
// ---------------------------------------------------------------------------
__global__ __launch_bounds__(256, 4) void k_reduce(float* __restrict__ out)
{
    int i = blockIdx.x * 256 + threadIdx.x;
    const float4* p = (const float4*)g_part;
    const int n4 = DM * SL / 4;
    float4 a = p[i], b = p[i + n4], c = p[i + 2 * n4], d = p[i + 3 * n4];
    float4 o;
    o.x = a.x + b.x + c.x + d.x;
    o.y = a.y + b.y + c.y + d.y;
    o.z = a.z + b.z + c.z + d.z;
    o.w = a.w + b.w + c.w + d.w;
    ((float4*)out)[i] = o;
}

// ---------------------------------------------------------------------------
extern "C" void kernel_launch(void* const* d_in, const int* in_sizes, int n_in,
                              void* d_out, int out_size)
{
    (void)in_sizes; (void)n_in; (void)out_size;
    const float* x  = (const float*)d_in[0];
    const float* Gs = (const float*)d_in[1];
    const float* GA = (const float*)d_in[2];
    const float* GB = (const float*)d_in[3];
    const float* Us = (const float*)d_in[4];
    const float* UA = (const float*)d_in[5];
    const float* UB = (const float*)d_in[6];
    const float* Ds = (const float*)d_in[7];
    const float* DA = (const float*)d_in[8];
    const float* DB = (const float*)d_in[9];
    float* out = (float*)d_out;

    float *wg, *wu, *wd;
    cudaGetSymbolAddress((void**)&wg, g_Wg);
    cudaGetSymbolAddress((void**)&wu, g_Wu);
    cudaGetSymbolAddress((void**)&wd, g_Wd);

    cudaFuncSetAttribute(k_gemm_gateup, cudaFuncAttributeMaxDynamicSharedMemorySize, K2_SMEM);
    cudaFuncSetAttribute(k_gemm_down,   cudaFuncAttributeMaxDynamicSharedMemorySize, K3_SMEM);

    k_dequant<<<dim3(DM / 128, DF / 32), 256>>>(Gs, GA, GB, wg, DM);
    k_dequant<<<dim3(DM / 128, DF / 32), 256>>>(Us, UA, UB, wu, DM);
    k_dequant<<<dim3(DF / 128, DM / 32), 256>>>(Ds, DA, DB, wd, DF);
    k_xt<<<dim3(DM / 32, SL / 32), 256>>>(x);

    k_gemm_gateup<<<dim3(DF / 128, SL / 128), 256, K2_SMEM>>>();
    k_gemm_down<<<dim3(DM / 128, SL / 128, 4), 256, K3_SMEM>>>();
    k_reduce<<<DM * SL / 4 / 256, 256>>>(out);
}

// round 7
// speedup vs baseline: 8.2468x; 1.5055x over previous
#include <cuda_runtime.h>
#include <cuda_fp16.h>
#include <cstdint>

#define DM 2048   // D_MODEL
#define DF 8192   // D_FF
#define RK 32     // RANK
#define SL 512    // S

// ---------------------------------------------------------------------------
// Global scratch
// ---------------------------------------------------------------------------
__device__ __half g_Wg[DF * DM];      // gate_eff fp16
__device__ __half g_Wu[DF * DM];      // up_eff fp16
__device__ __half g_Wd[DM * DF];      // down_eff fp16
__device__ __half g_xT[SL * DM];      // x transposed [s][c] fp16
__device__ __half g_mlpT[SL * DF];    // silu(g)*u transposed [s][ff] fp16
__device__ float  g_part[4 * DM * SL];// split-K partials (fp32)

// ---------------------------------------------------------------------------
// Helpers
// ---------------------------------------------------------------------------
__device__ __forceinline__ float to_tf32(float x) {
    uint32_t u;
    asm("cvt.rna.tf32.f32 %0, %1;" : "=r"(u) : "f"(x));
    return __uint_as_float(u);
}
__device__ __forceinline__ uint32_t smem_u32(const void* p) {
    uint32_t a;
    asm("{ .reg .u64 t; cvta.to.shared.u64 t, %1; cvt.u32.u64 %0, t; }" : "=r"(a) : "l"(p));
    return a;
}
__device__ __forceinline__ void cp16(uint32_t dst, const void* src) {
    asm volatile("cp.async.cg.shared.global [%0], [%1], 16;" :: "r"(dst), "l"(src));
}
__device__ __forceinline__ void cp_commit() { asm volatile("cp.async.commit_group;"); }
__device__ __forceinline__ void cp_wait1()  { asm volatile("cp.async.wait_group 1;" ::: "memory"); }
__device__ __forceinline__ void cp_wait0()  { asm volatile("cp.async.wait_group 0;" ::: "memory"); }

// tf32 m16n8k8 (used for dequant scale GEMM)
__device__ __forceinline__ void mma8(float* c, const float* a, const float* b) {
    asm volatile(
        "mma.sync.aligned.m16n8k8.row.col.f32.tf32.tf32.f32 "
        "{%0,%1,%2,%3}, {%4,%5,%6,%7}, {%8,%9}, {%0,%1,%2,%3};"
        : "+f"(c[0]), "+f"(c[1]), "+f"(c[2]), "+f"(c[3])
        : "r"(__float_as_uint(a[0])), "r"(__float_as_uint(a[1])),
          "r"(__float_as_uint(a[2])), "r"(__float_as_uint(a[3])),
          "r"(__float_as_uint(b[0])), "r"(__float_as_uint(b[1])));
}
// fp16 m16n8k16 (main GEMMs), fp32 accum
__device__ __forceinline__ void mma16(float* c, const uint32_t* a, const uint32_t* b) {
    asm volatile(
        "mma.sync.aligned.m16n8k16.row.col.f32.f16.f16.f32 "
        "{%0,%1,%2,%3}, {%4,%5,%6,%7}, {%8,%9}, {%0,%1,%2,%3};"
        : "+f"(c[0]), "+f"(c[1]), "+f"(c[2]), "+f"(c[3])
        : "r"(a[0]), "r"(a[1]), "r"(a[2]), "r"(a[3]), "r"(b[0]), "r"(b[1]));
}

#define PADH 40                    // 32 k-halves padded to 40 (16B-aligned, conflict-free)
#define TILE_H (128 * PADH * 2)    // 10240 B per 128-row half tile

// ---------------------------------------------------------------------------
// Kernel 1: dequant  W' = fp16( Ws .* (A @ B) ).  CTA tile: 128 rows x 128 cols.
// Scale tile via tf32 mma; then memory-bound multiply/convert pass.
// ---------------------------------------------------------------------------
#define DQ_SMEM 67584

__global__ __launch_bounds__(256, 1) void k_dequant(
    const float* __restrict__ Ws, const float* __restrict__ Aa,
    const float* __restrict__ Bb, __half* __restrict__ Wo, int cols)
{
    extern __shared__ float dsm[];
    float* sA = dsm;                    // [128][36] rows=f, cols=rank
    float* sB = dsm + 128 * 36;         // [128][36] rows=c, cols=rank (transposed B)
    int tid = threadIdx.x, wid = tid >> 5, lane = tid & 31;
    int g = lane >> 2, tg = lane & 3;
    int wm = wid & 3, wn = wid >> 2;
    int cb = blockIdx.x * 128, fb = blockIdx.y * 128;

    #pragma unroll
    for (int t = 0; t < 16; t++) {
        int idx = tid + t * 256;        // 0..4095
        int r = idx >> 5, k = idx & 31;
        sA[r * 36 + k] = to_tf32(Aa[(fb + r) * RK + k]);
        int rr = idx >> 7, c = idx & 127;
        sB[c * 36 + rr] = to_tf32(Bb[rr * cols + cb + c]);
    }
    __syncthreads();

    float acc[2][8][4];
    #pragma unroll
    for (int mt = 0; mt < 2; mt++)
        #pragma unroll
        for (int nt = 0; nt < 8; nt++)
            #pragma unroll
            for (int i = 0; i < 4; i++) acc[mt][nt][i] = 0.f;

    #pragma unroll
    for (int ks = 0; ks < 4; ks++) {
        int k0 = ks * 8;
        float bq[8][2];
        #pragma unroll
        for (int nt = 0; nt < 8; nt++) {
            const float* bp = sB + (wn * 64 + nt * 8 + g) * 36 + k0 + tg;
            bq[nt][0] = bp[0]; bq[nt][1] = bp[4];
        }
        #pragma unroll
        for (int mt = 0; mt < 2; mt++) {
            const float* ap = sA + (wm * 32 + mt * 16 + g) * 36 + k0 + tg;
            float a[4] = { ap[0], ap[8 * 36], ap[4], ap[8 * 36 + 4] };
            #pragma unroll
            for (int nt = 0; nt < 8; nt++) mma8(acc[mt][nt], a, bq[nt]);
        }
    }
    __syncthreads();   // done reading sA/sB; reuse smem for scale stage

    float* sS = dsm;   // [128][132]
    #pragma unroll
    for (int mt = 0; mt < 2; mt++)
        #pragma unroll
        for (int nt = 0; nt < 8; nt++) {
            int r0 = wm * 32 + mt * 16 + g;
            int c0 = wn * 64 + nt * 8 + 2 * tg;
            #pragma unroll
            for (int i = 0; i < 4; i++)
                sS[(r0 + (i >> 1) * 8) * 132 + c0 + (i & 1)] = acc[mt][nt][i];
        }
    __syncthreads();

    // memory pass: W' = fp16(Ws * scale)
    #pragma unroll
    for (int t = 0; t < 16; t++) {
        int idx = tid + t * 256;        // 0..4095 float4 groups
        int r = idx >> 5, c4 = idx & 31;
        const float4 w = *(const float4*)&Ws[(fb + r) * cols + cb + c4 * 4];
        const float4 s = *(const float4*)&sS[r * 132 + c4 * 4];
        __half2 lo = __floats2half2_rn(w.x * s.x, w.y * s.y);
        __half2 hi = __floats2half2_rn(w.z * s.z, w.w * s.w);
        uint2 o = { *(uint32_t*)&lo, *(uint32_t*)&hi };
        *(uint2*)&Wo[(fb + r) * cols + cb + c4 * 4] = o;
    }
}

// ---------------------------------------------------------------------------
// x transpose -> fp16
// ---------------------------------------------------------------------------
__global__ __launch_bounds__(256, 4) void k_xt(const float* __restrict__ x)
{
    __shared__ float sm[32][33];
    int tid = threadIdx.x, tx = tid & 31, ty = tid >> 5;
    int cb = blockIdx.x * 32, sb = blockIdx.y * 32;
    #pragma unroll
    for (int i = 0; i < 4; i++)
        sm[ty + i * 8][tx] = x[(cb + ty + i * 8) * SL + sb + tx];
    __syncthreads();
    #pragma unroll
    for (int i = 0; i < 4; i++)
        g_xT[(sb + ty + i * 8) * DM + cb + tx] = __float2half_rn(sm[tx][ty + i * 8]);
}

// ---------------------------------------------------------------------------
// Half-tile stage loader: 128 rows x 32 k-halves -> [row][PADH] layout
// ---------------------------------------------------------------------------
__device__ __forceinline__ void load_tile_h(uint32_t dst, const __half* __restrict__ src,
                                            int row_base, int ld, int c0, int tid)
{
    #pragma unroll
    for (int t = 0; t < 2; t++) {
        int id = tid + t * 256;         // 0..511
        int r = id >> 2, cbk = id & 3;
        cp16(dst + (r * PADH + cbk * 8) * 2, src + (row_base + r) * ld + c0 + cbk * 8);
    }
}

// ---------------------------------------------------------------------------
// Kernel 2: gate+up fp16 GEMM + SwiGLU -> g_mlpT (fp16)
// CTA: 128 f x 128 s, BK=32. grid(x=s-tile, y=f-tile) for L2 weight reuse.
// SMEM/stage: Ag | Au | Bx (3 x 10240 B), double-buffered = 61440 B.
// ---------------------------------------------------------------------------
#define K2_STG (3 * TILE_H)
#define K2_SMEM (2 * K2_STG)

__global__ __launch_bounds__(256, 1) void k_gemm_gateup()
{
    extern __shared__ char smemc[];
    __half* smh = (__half*)smemc;
    const uint32_t su = smem_u32(smemc);
    const int tid = threadIdx.x, wid = tid >> 5, lane = tid & 31;
    const int g = lane >> 2, tg = lane & 3;
    const int warp_m = wid & 3, warp_n = wid >> 2;
    const int sb = blockIdx.x * 128, fbase = blockIdx.y * 128;

    float accg[2][8][4], accu[2][8][4];
    #pragma unroll
    for (int mt = 0; mt < 2; mt++)
        #pragma unroll
        for (int nt = 0; nt < 8; nt++)
            #pragma unroll
            for (int i = 0; i < 4; i++) { accg[mt][nt][i] = 0.f; accu[mt][nt][i] = 0.f; }

    load_tile_h(su,              g_Wg, fbase, DM, 0, tid);
    load_tile_h(su + TILE_H,     g_Wu, fbase, DM, 0, tid);
    load_tile_h(su + 2 * TILE_H, g_xT, sb,    DM, 0, tid);
    cp_commit();

    for (int i = 0; i < 64; i++) {
        if (i < 63) {
            uint32_t b = su + ((i + 1) & 1) * K2_STG;
            int c0 = (i + 1) * 32;
            load_tile_h(b,              g_Wg, fbase, DM, c0, tid);
            load_tile_h(b + TILE_H,     g_Wu, fbase, DM, c0, tid);
            load_tile_h(b + 2 * TILE_H, g_xT, sb,    DM, c0, tid);
            cp_commit();
            cp_wait1();
        } else {
            cp_wait0();
        }
        __syncthreads();

        const __half* Ag = smh + (i & 1) * (K2_STG / 2);
        const __half* Au = Ag + TILE_H / 2;
        const __half* Bx = Ag + 2 * (TILE_H / 2);

        #pragma unroll
        for (int ks = 0; ks < 2; ks++) {
            const int k0 = ks * 16;
            uint32_t bq[8][2];
            #pragma unroll
            for (int nt = 0; nt < 8; nt++) {
                const __half* bp = Bx + (warp_n * 64 + nt * 8 + g) * PADH + k0 + 2 * tg;
                bq[nt][0] = *(const uint32_t*)bp;
                bq[nt][1] = *(const uint32_t*)(bp + 8);
            }
            #pragma unroll
            for (int mt = 0; mt < 2; mt++) {
                const __half* agp = Ag + (warp_m * 32 + mt * 16 + g) * PADH + k0 + 2 * tg;
                const __half* aup = Au + (warp_m * 32 + mt * 16 + g) * PADH + k0 + 2 * tg;
                uint32_t ag[4] = { *(const uint32_t*)agp, *(const uint32_t*)(agp + 8 * PADH),
                                   *(const uint32_t*)(agp + 8), *(const uint32_t*)(agp + 8 * PADH + 8) };
                uint32_t au[4] = { *(const uint32_t*)aup, *(const uint32_t*)(aup + 8 * PADH),
                                   *(const uint32_t*)(aup + 8), *(const uint32_t*)(aup + 8 * PADH + 8) };
                #pragma unroll
                for (int nt = 0; nt < 8; nt++) {
                    mma16(accg[mt][nt], ag, bq[nt]);
                    mma16(accu[mt][nt], au, bq[nt]);
                }
            }
        }
        __syncthreads();
    }

    // epilogue: SwiGLU, transpose via smem (half), coalesced write
    __half* so = smh;   // [s 128][f pad 136] halves = 34816 B
    #pragma unroll
    for (int mt = 0; mt < 2; mt++)
        #pragma unroll
        for (int nt = 0; nt < 8; nt++) {
            int r0 = warp_m * 32 + mt * 16 + g;
            int c0 = warp_n * 64 + nt * 8 + 2 * tg;
            #pragma unroll
            for (int i = 0; i < 4; i++) {
                float gg = accg[mt][nt][i], uu = accu[mt][nt][i];
                float m = (gg / (1.f + __expf(-gg))) * uu;
                so[(c0 + (i & 1)) * 136 + r0 + (i >> 1) * 8] = __float2half_rn(m);
            }
        }
    __syncthreads();
    #pragma unroll
    for (int t = 0; t < 32; t++) {
        int idx = tid + t * 256;        // 0..8191 half2 units
        int s = idx >> 6, f2 = idx & 63;
        uint32_t v = *(const uint32_t*)&so[s * 136 + f2 * 2];
        *(uint32_t*)&g_mlpT[(sb + s) * DF + fbase + f2 * 2] = v;
    }
}

// ---------------------------------------------------------------------------
// Kernel 3: down fp16 GEMM, split-K=4 -> g_part.  CTA: 128 m x 128 s.
// grid(x=s 4, y=m 16, z=k 4).  SMEM/stage: Ad | Bm (2 x 10240 B).
// ---------------------------------------------------------------------------
#define K3_STG (2 * TILE_H)
#define K3_SMEM 67584   // max(2 stages = 40960, epilogue stage 128*132*4)

__global__ __launch_bounds__(256, 1) void k_gemm_down()
{
    extern __shared__ char smemc[];
    __half* smh = (__half*)smemc;
    const uint32_t su = smem_u32(smemc);
    const int tid = threadIdx.x, wid = tid >> 5, lane = tid & 31;
    const int g = lane >> 2, tg = lane & 3;
    const int warp_m = wid & 3, warp_n = wid >> 2;
    const int sb = blockIdx.x * 128, mbase = blockIdx.y * 128;
    const int kbase = blockIdx.z * 2048;

    float acc[2][8][4];
    #pragma unroll
    for (int mt = 0; mt < 2; mt++)
        #pragma unroll
        for (int nt = 0; nt < 8; nt++)
            #pragma unroll
            for (int i = 0; i < 4; i++) acc[mt][nt][i] = 0.f;

    load_tile_h(su,          g_Wd,   mbase, DF, kbase, tid);
    load_tile_h(su + TILE_H, g_mlpT, sb,    DF, kbase, tid);
    cp_commit();

    for (int i = 0; i < 64; i++) {
        if (i < 63) {
            uint32_t b = su + ((i + 1) & 1) * K3_STG;
            int c0 = kbase + (i + 1) * 32;
            load_tile_h(b,          g_Wd,   mbase, DF, c0, tid);
            load_tile_h(b + TILE_H, g_mlpT, sb,    DF, c0, tid);
            cp_commit();
            cp_wait1();
        } else {
            cp_wait0();
        }
        __syncthreads();

        const __half* Ad = smh + (i & 1) * (K3_STG / 2);
        const __half* Bm = Ad + TILE_H / 2;

        #pragma unroll
        for (int ks = 0; ks < 2; ks++) {
            const int k0 = ks * 16;
            uint32_t bq[8][2];
            #pragma unroll
            for (int nt = 0; nt < 8; nt++) {
                const __half* bp = Bm + (warp_n * 64 + nt * 8 + g) * PADH + k0 + 2 * tg;
                bq[nt][0] = *(const uint32_t*)bp;
                bq[nt][1] = *(const uint32_t*)(bp + 8);
            }
            #pragma unroll
            for (int mt = 0; mt < 2; mt++) {
                const __half* ap = Ad + (warp_m * 32 + mt * 16 + g) * PADH + k0 + 2 * tg;
                uint32_t a[4] = { *(const uint32_t*)ap, *(const uint32_t*)(ap + 8 * PADH),
                                  *(const uint32_t*)(ap + 8), *(const uint32_t*)(ap + 8 * PADH + 8) };
                #pragma unroll
                for (int nt = 0; nt < 8; nt++) mma16(acc[mt][nt], a, bq[nt]);
            }
        }
        __syncthreads();
    }

    // epilogue: stage [m][s] in smem (fp32), coalesced float4 partial writes
    float* so = (float*)smemc;   // [128][132]
    #pragma unroll
    for (int mt = 0; mt < 2; mt++)
        #pragma unroll
        for (int nt = 0; nt < 8; nt++) {
            int r0 = warp_m * 32 + mt * 16 + g;
            int c0 = warp_n * 64 + nt * 8 + 2 * tg;
            #pragma unroll
            for (int i = 0; i < 4; i++)
                so[(r0 + (i >> 1) * 8) * 132 + c0 + (i & 1)] = acc[mt][nt][i];
        }
    __syncthreads();
    #pragma unroll
    for (int t = 0; t < 16; t++) {
        int idx = tid + t * 256;        // float4 groups
        int m = idx >> 5, c4 = idx & 31;
        float4 v = *(const float4*)&so[m * 132 + c4 * 4];
        *(float4*)&g_part[(blockIdx.z * DM + mbase + m) * SL + sb + c4 * 4] = v;
    }
}

// ---------------------------------------------------------------------------
// Kernel 4: split-K reduce
// ---------------------------------------------------------------------------
__global__ __launch_bounds__(256, 4) void k_reduce(float* __restrict__ out)
{
    int i = blockIdx.x * 256 + threadIdx.x;
    const float4* p = (const float4*)g_part;
    const int n4 = DM * SL / 4;
    float4 a = p[i], b = p[i + n4], c = p[i + 2 * n4], d = p[i + 3 * n4];
    float4 o;
    o.x = a.x + b.x + c.x + d.x;
    o.y = a.y + b.y + c.y + d.y;
    o.z = a.z + b.z + c.z + d.z;
    o.w = a.w + b.w + c.w + d.w;
    ((float4*)out)[i] = o;
}

// ---------------------------------------------------------------------------
extern "C" void kernel_launch(void* const* d_in, const int* in_sizes, int n_in,
                              void* d_out, int out_size)
{
    (void)in_sizes; (void)n_in; (void)out_size;
    const float* x  = (const float*)d_in[0];
    const float* Gs = (const float*)d_in[1];
    const float* GA = (const float*)d_in[2];
    const float* GB = (const float*)d_in[3];
    const float* Us = (const float*)d_in[4];
    const float* UA = (const float*)d_in[5];
    const float* UB = (const float*)d_in[6];
    const float* Ds = (const float*)d_in[7];
    const float* DA = (const float*)d_in[8];
    const float* DB = (const float*)d_in[9];
    float* out = (float*)d_out;

    __half *wg, *wu, *wd;
    cudaGetSymbolAddress((void**)&wg, g_Wg);
    cudaGetSymbolAddress((void**)&wu, g_Wu);
    cudaGetSymbolAddress((void**)&wd, g_Wd);

    cudaFuncSetAttribute(k_dequant,     cudaFuncAttributeMaxDynamicSharedMemorySize, DQ_SMEM);
    cudaFuncSetAttribute(k_gemm_gateup, cudaFuncAttributeMaxDynamicSharedMemorySize, K2_SMEM);
    cudaFuncSetAttribute(k_gemm_down,   cudaFuncAttributeMaxDynamicSharedMemorySize, K3_SMEM);

    k_dequant<<<dim3(DM / 128, DF / 128), 256, DQ_SMEM>>>(Gs, GA, GB, wg, DM);
    k_dequant<<<dim3(DM / 128, DF / 128), 256, DQ_SMEM>>>(Us, UA, UB, wu, DM);
    k_dequant<<<dim3(DF / 128, DM / 128), 256, DQ_SMEM>>>(Ds, DA, DB, wd, DF);
    k_xt<<<dim3(DM / 32, SL / 32), 256>>>(x);

    k_gemm_gateup<<<dim3(SL / 128, DF / 128), 256, K2_SMEM>>>();
    k_gemm_down<<<dim3(SL / 128, DM / 128, 4), 256, K3_SMEM>>>();
    k_reduce<<<DM * SL / 4 / 256, 256>>>(out);
}

// round 8
// speedup vs baseline: 9.2765x; 1.1249x over previous
#include <cuda_runtime.h>
#include <cuda_fp16.h>
#include <cstdint>

#define DM 2048   // D_MODEL
#define DF 8192   // D_FF
#define RK 32     // RANK
#define SL 512    // S

// ---------------------------------------------------------------------------
// Global scratch
// ---------------------------------------------------------------------------
__device__ __half g_Wg[DF * DM];      // gate_eff fp16
__device__ __half g_Wu[DF * DM];      // up_eff fp16
__device__ __half g_Wd[DM * DF];      // down_eff fp16
__device__ __half g_xT[SL * DM];      // x transposed [s][c] fp16
__device__ __half g_mlpT[SL * DF];    // silu(g)*u transposed [s][ff] fp16
__device__ float  g_part[4 * DM * SL];// split-K partials (fp32)

// ---------------------------------------------------------------------------
// Helpers
// ---------------------------------------------------------------------------
__device__ __forceinline__ float to_tf32(float x) {
    uint32_t u;
    asm("cvt.rna.tf32.f32 %0, %1;" : "=r"(u) : "f"(x));
    return __uint_as_float(u);
}
__device__ __forceinline__ uint32_t smem_u32(const void* p) {
    uint32_t a;
    asm("{ .reg .u64 t; cvta.to.shared.u64 t, %1; cvt.u32.u64 %0, t; }" : "=r"(a) : "l"(p));
    return a;
}
__device__ __forceinline__ void cp16(uint32_t dst, const void* src) {
    asm volatile("cp.async.cg.shared.global [%0], [%1], 16;" :: "r"(dst), "l"(src));
}
__device__ __forceinline__ void cp_commit() { asm volatile("cp.async.commit_group;"); }
__device__ __forceinline__ void cp_wait1()  { asm volatile("cp.async.wait_group 1;" ::: "memory"); }
__device__ __forceinline__ void cp_wait0()  { asm volatile("cp.async.wait_group 0;" ::: "memory"); }

// tf32 m16n8k8 (dequant scale GEMM)
__device__ __forceinline__ void mma8(float* c, const float* a, const float* b) {
    asm volatile(
        "mma.sync.aligned.m16n8k8.row.col.f32.tf32.tf32.f32 "
        "{%0,%1,%2,%3}, {%4,%5,%6,%7}, {%8,%9}, {%0,%1,%2,%3};"
        : "+f"(c[0]), "+f"(c[1]), "+f"(c[2]), "+f"(c[3])
        : "r"(__float_as_uint(a[0])), "r"(__float_as_uint(a[1])),
          "r"(__float_as_uint(a[2])), "r"(__float_as_uint(a[3])),
          "r"(__float_as_uint(b[0])), "r"(__float_as_uint(b[1])));
}
// fp16 m16n8k16 (main GEMMs), fp32 accum
__device__ __forceinline__ void mma16(float* c, const uint32_t* a, const uint32_t* b) {
    asm volatile(
        "mma.sync.aligned.m16n8k16.row.col.f32.f16.f16.f32 "
        "{%0,%1,%2,%3}, {%4,%5,%6,%7}, {%8,%9}, {%0,%1,%2,%3};"
        : "+f"(c[0]), "+f"(c[1]), "+f"(c[2]), "+f"(c[3])
        : "r"(a[0]), "r"(a[1]), "r"(a[2]), "r"(a[3]), "r"(b[0]), "r"(b[1]));
}
__device__ __forceinline__ void ldsm4(uint32_t* r, uint32_t addr) {
    asm volatile("ldmatrix.sync.aligned.m8n8.x4.shared.b16 {%0,%1,%2,%3}, [%4];"
                 : "=r"(r[0]), "=r"(r[1]), "=r"(r[2]), "=r"(r[3]) : "r"(addr));
}

// BK=64 tile: 128 rows x 64 k-halves padded to 72 (row stride 144 B; 144 % 16 == 0,
// and 144 mod 128 = 16 -> 8 consecutive rows cover all 32 banks: ldmatrix conflict-free)
#define PADH 72
#define TILE_H (128 * PADH * 2)    // 18432 B

// ---------------------------------------------------------------------------
// Kernel 1: dequant  W' = fp16( Ws .* (A @ B) ).  CTA tile: 128 rows x 128 cols.
// ---------------------------------------------------------------------------
#define DQ_SMEM 67584

__global__ __launch_bounds__(256, 1) void k_dequant(
    const float* __restrict__ Ws, const float* __restrict__ Aa,
    const float* __restrict__ Bb, __half* __restrict__ Wo, int cols)
{
    extern __shared__ float dsm[];
    float* sA = dsm;                    // [128][36] rows=f, cols=rank
    float* sB = dsm + 128 * 36;         // [128][36] rows=c, cols=rank (transposed B)
    int tid = threadIdx.x, wid = tid >> 5, lane = tid & 31;
    int g = lane >> 2, tg = lane & 3;
    int wm = wid & 3, wn = wid >> 2;
    int cb = blockIdx.x * 128, fb = blockIdx.y * 128;

    #pragma unroll
    for (int t = 0; t < 16; t++) {
        int idx = tid + t * 256;
        int r = idx >> 5, k = idx & 31;
        sA[r * 36 + k] = to_tf32(Aa[(fb + r) * RK + k]);
        int rr = idx >> 7, c = idx & 127;
        sB[c * 36 + rr] = to_tf32(Bb[rr * cols + cb + c]);
    }
    __syncthreads();

    float acc[2][8][4];
    #pragma unroll
    for (int mt = 0; mt < 2; mt++)
        #pragma unroll
        for (int nt = 0; nt < 8; nt++)
            #pragma unroll
            for (int i = 0; i < 4; i++) acc[mt][nt][i] = 0.f;

    #pragma unroll
    for (int ks = 0; ks < 4; ks++) {
        int k0 = ks * 8;
        float bq[8][2];
        #pragma unroll
        for (int nt = 0; nt < 8; nt++) {
            const float* bp = sB + (wn * 64 + nt * 8 + g) * 36 + k0 + tg;
            bq[nt][0] = bp[0]; bq[nt][1] = bp[4];
        }
        #pragma unroll
        for (int mt = 0; mt < 2; mt++) {
            const float* ap = sA + (wm * 32 + mt * 16 + g) * 36 + k0 + tg;
            float a[4] = { ap[0], ap[8 * 36], ap[4], ap[8 * 36 + 4] };
            #pragma unroll
            for (int nt = 0; nt < 8; nt++) mma8(acc[mt][nt], a, bq[nt]);
        }
    }
    __syncthreads();

    float* sS = dsm;   // [128][132]
    #pragma unroll
    for (int mt = 0; mt < 2; mt++)
        #pragma unroll
        for (int nt = 0; nt < 8; nt++) {
            int r0 = wm * 32 + mt * 16 + g;
            int c0 = wn * 64 + nt * 8 + 2 * tg;
            #pragma unroll
            for (int i = 0; i < 4; i++)
                sS[(r0 + (i >> 1) * 8) * 132 + c0 + (i & 1)] = acc[mt][nt][i];
        }
    __syncthreads();

    #pragma unroll
    for (int t = 0; t < 16; t++) {
        int idx = tid + t * 256;
        int r = idx >> 5, c4 = idx & 31;
        const float4 w = *(const float4*)&Ws[(fb + r) * cols + cb + c4 * 4];
        const float4 s = *(const float4*)&sS[r * 132 + c4 * 4];
        __half2 lo = __floats2half2_rn(w.x * s.x, w.y * s.y);
        __half2 hi = __floats2half2_rn(w.z * s.z, w.w * s.w);
        uint2 o = { *(uint32_t*)&lo, *(uint32_t*)&hi };
        *(uint2*)&Wo[(fb + r) * cols + cb + c4 * 4] = o;
    }
}

// ---------------------------------------------------------------------------
// x transpose -> fp16
// ---------------------------------------------------------------------------
__global__ __launch_bounds__(256, 4) void k_xt(const float* __restrict__ x)
{
    __shared__ float sm[32][33];
    int tid = threadIdx.x, tx = tid & 31, ty = tid >> 5;
    int cb = blockIdx.x * 32, sb = blockIdx.y * 32;
    #pragma unroll
    for (int i = 0; i < 4; i++)
        sm[ty + i * 8][tx] = x[(cb + ty + i * 8) * SL + sb + tx];
    __syncthreads();
    #pragma unroll
    for (int i = 0; i < 4; i++)
        g_xT[(sb + ty + i * 8) * DM + cb + tx] = __float2half_rn(sm[tx][ty + i * 8]);
}

// ---------------------------------------------------------------------------
// Stage loader: 128 rows x 64 k-halves -> [row][PADH]; 4 cp16 per thread
// ---------------------------------------------------------------------------
__device__ __forceinline__ void load_tile64(uint32_t dst, const __half* __restrict__ src,
                                            int row_base, int ld, int c0, int tid)
{
    #pragma unroll
    for (int t = 0; t < 4; t++) {
        int id = tid + t * 256;         // 0..1023
        int r = id >> 3, cbk = id & 7;
        cp16(dst + (r * PADH + cbk * 8) * 2, src + (row_base + r) * ld + c0 + cbk * 8);
    }
}

// ldmatrix per-lane byte offsets within a tile
// A (16x16 from rows base..base+15): lane l -> row (l&15), col-half (l>>4)
__device__ __forceinline__ uint32_t a_off(int lane, int row_base) {
    return (uint32_t)((row_base + (lane & 15)) * (PADH * 2) + ((lane >> 4) * 16));
}
// B (two n-tiles of 8 rows, 16 k): lane l -> n-row (l>>4)*8 + (l&7), col-half ((l>>3)&1)
__device__ __forceinline__ uint32_t b_off(int lane, int row_base) {
    return (uint32_t)((row_base + ((lane >> 4) * 8) + (lane & 7)) * (PADH * 2) +
                      (((lane >> 3) & 1) * 16));
}

// ---------------------------------------------------------------------------
// Kernel 2: gate+up fp16 GEMM + SwiGLU -> g_mlpT (fp16)
// CTA: 128 f x 128 s, BK=64, 32 iters, ldmatrix fragments.
// SMEM/stage: Ag | Au | Bx (3 x 18432 B), double-buffered = 110592 B.
// ---------------------------------------------------------------------------
#define K2_STG (3 * TILE_H)
#define K2_SMEM (2 * K2_STG)

__global__ __launch_bounds__(256, 1) void k_gemm_gateup()
{
    extern __shared__ char smemc[];
    __half* smh = (__half*)smemc;
    const uint32_t su = smem_u32(smemc);
    const int tid = threadIdx.x, wid = tid >> 5, lane = tid & 31;
    const int g = lane >> 2, tg = lane & 3;
    const int warp_m = wid & 3, warp_n = wid >> 2;
    const int sb = blockIdx.x * 128, fbase = blockIdx.y * 128;

    const uint32_t rA = a_off(lane, warp_m * 32);   // + mt*16 rows -> + mt*2304
    const uint32_t rB = b_off(lane, warp_n * 64);   // + pair*16 rows -> + p*2304

    float accg[2][8][4], accu[2][8][4];
    #pragma unroll
    for (int mt = 0; mt < 2; mt++)
        #pragma unroll
        for (int nt = 0; nt < 8; nt++)
            #pragma unroll
            for (int i = 0; i < 4; i++) { accg[mt][nt][i] = 0.f; accu[mt][nt][i] = 0.f; }

    load_tile64(su,              g_Wg, fbase, DM, 0, tid);
    load_tile64(su + TILE_H,     g_Wu, fbase, DM, 0, tid);
    load_tile64(su + 2 * TILE_H, g_xT, sb,    DM, 0, tid);
    cp_commit();

    for (int i = 0; i < 32; i++) {
        if (i < 31) {
            uint32_t b = su + ((i + 1) & 1) * K2_STG;
            int c0 = (i + 1) * 64;
            load_tile64(b,              g_Wg, fbase, DM, c0, tid);
            load_tile64(b + TILE_H,     g_Wu, fbase, DM, c0, tid);
            load_tile64(b + 2 * TILE_H, g_xT, sb,    DM, c0, tid);
            cp_commit();
            cp_wait1();
        } else {
            cp_wait0();
        }
        __syncthreads();

        const uint32_t bAg = su + (i & 1) * K2_STG;
        const uint32_t bAu = bAg + TILE_H;
        const uint32_t bBx = bAg + 2 * TILE_H;

        #pragma unroll
        for (int ks = 0; ks < 4; ks++) {
            const uint32_t kb = ks * 32;   // 16 halves = 32 bytes
            uint32_t bq[4][4];
            #pragma unroll
            for (int p = 0; p < 4; p++)
                ldsm4(bq[p], bBx + rB + p * 2304 + kb);
            #pragma unroll
            for (int mt = 0; mt < 2; mt++) {
                uint32_t ag[4], au[4];
                ldsm4(ag, bAg + rA + mt * 2304 + kb);
                ldsm4(au, bAu + rA + mt * 2304 + kb);
                #pragma unroll
                for (int p = 0; p < 4; p++) {
                    mma16(accg[mt][2 * p],     ag, &bq[p][0]);
                    mma16(accg[mt][2 * p + 1], ag, &bq[p][2]);
                    mma16(accu[mt][2 * p],     au, &bq[p][0]);
                    mma16(accu[mt][2 * p + 1], au, &bq[p][2]);
                }
            }
        }
        __syncthreads();
    }

    // epilogue: SwiGLU, transpose via smem (half), coalesced write
    __half* so = smh;   // [s 128][f pad 136] halves = 34816 B
    #pragma unroll
    for (int mt = 0; mt < 2; mt++)
        #pragma unroll
        for (int nt = 0; nt < 8; nt++) {
            int r0 = warp_m * 32 + mt * 16 + g;
            int c0 = warp_n * 64 + nt * 8 + 2 * tg;
            #pragma unroll
            for (int i = 0; i < 4; i++) {
                float gg = accg[mt][nt][i], uu = accu[mt][nt][i];
                float m = (gg / (1.f + __expf(-gg))) * uu;
                so[(c0 + (i & 1)) * 136 + r0 + (i >> 1) * 8] = __float2half_rn(m);
            }
        }
    __syncthreads();
    #pragma unroll
    for (int t = 0; t < 32; t++) {
        int idx = tid + t * 256;
        int s = idx >> 6, f2 = idx & 63;
        uint32_t v = *(const uint32_t*)&so[s * 136 + f2 * 2];
        *(uint32_t*)&g_mlpT[(sb + s) * DF + fbase + f2 * 2] = v;
    }
}

// ---------------------------------------------------------------------------
// Kernel 3: down fp16 GEMM, split-K=4 -> g_part.  CTA: 128 m x 128 s, BK=64.
// SMEM/stage: Ad | Bm (2 x 18432 B), double-buffered = 73728 B.
// ---------------------------------------------------------------------------
#define K3_STG (2 * TILE_H)
#define K3_SMEM (2 * K3_STG)

__global__ __launch_bounds__(256, 1) void k_gemm_down()
{
    extern __shared__ char smemc[];
    const uint32_t su = smem_u32(smemc);
    const int tid = threadIdx.x, wid = tid >> 5, lane = tid & 31;
    const int g = lane >> 2, tg = lane & 3;
    const int warp_m = wid & 3, warp_n = wid >> 2;
    const int sb = blockIdx.x * 128, mbase = blockIdx.y * 128;
    const int kbase = blockIdx.z * 2048;

    const uint32_t rA = a_off(lane, warp_m * 32);
    const uint32_t rB = b_off(lane, warp_n * 64);

    float acc[2][8][4];
    #pragma unroll
    for (int mt = 0; mt < 2; mt++)
        #pragma unroll
        for (int nt = 0; nt < 8; nt++)
            #pragma unroll
            for (int i = 0; i < 4; i++) acc[mt][nt][i] = 0.f;

    load_tile64(su,          g_Wd,   mbase, DF, kbase, tid);
    load_tile64(su + TILE_H, g_mlpT, sb,    DF, kbase, tid);
    cp_commit();

    for (int i = 0; i < 32; i++) {
        if (i < 31) {
            uint32_t b = su + ((i + 1) & 1) * K3_STG;
            int c0 = kbase + (i + 1) * 64;
            load_tile64(b,          g_Wd,   mbase, DF, c0, tid);
            load_tile64(b + TILE_H, g_mlpT, sb,    DF, c0, tid);
            cp_commit();
            cp_wait1();
        } else {
            cp_wait0();
        }
        __syncthreads();

        const uint32_t bAd = su + (i & 1) * K3_STG;
        const uint32_t bBm = bAd + TILE_H;

        #pragma unroll
        for (int ks = 0; ks < 4; ks++) {
            const uint32_t kb = ks * 32;
            uint32_t bq[4][4];
            #pragma unroll
            for (int p = 0; p < 4; p++)
                ldsm4(bq[p], bBm + rB + p * 2304 + kb);
            #pragma unroll
            for (int mt = 0; mt < 2; mt++) {
                uint32_t a[4];
                ldsm4(a, bAd + rA + mt * 2304 + kb);
                #pragma unroll
                for (int p = 0; p < 4; p++) {
                    mma16(acc[mt][2 * p],     a, &bq[p][0]);
                    mma16(acc[mt][2 * p + 1], a, &bq[p][2]);
                }
            }
        }
        __syncthreads();
    }

    // epilogue: stage [m][s] in smem (fp32), coalesced float4 partial writes
    float* so = (float*)smemc;   // [128][132] = 67584 B < K3_SMEM
    #pragma unroll
    for (int mt = 0; mt < 2; mt++)
        #pragma unroll
        for (int nt = 0; nt < 8; nt++) {
            int r0 = warp_m * 32 + mt * 16 + g;
            int c0 = warp_n * 64 + nt * 8 + 2 * tg;
            #pragma unroll
            for (int i = 0; i < 4; i++)
                so[(r0 + (i >> 1) * 8) * 132 + c0 + (i & 1)] = acc[mt][nt][i];
        }
    __syncthreads();
    #pragma unroll
    for (int t = 0; t < 16; t++) {
        int idx = tid + t * 256;
        int m = idx >> 5, c4 = idx & 31;
        float4 v = *(const float4*)&so[m * 132 + c4 * 4];
        *(float4*)&g_part[(blockIdx.z * DM + mbase + m) * SL + sb + c4 * 4] = v;
    }
}

// ---------------------------------------------------------------------------
// Kernel 4: split-K reduce
// ---------------------------------------------------------------------------
__global__ __launch_bounds__(256, 4) void k_reduce(float* __restrict__ out)
{
    int i = blockIdx.x * 256 + threadIdx.x;
    const float4* p = (const float4*)g_part;
    const int n4 = DM * SL / 4;
    float4 a = p[i], b = p[i + n4], c = p[i + 2 * n4], d = p[i + 3 * n4];
    float4 o;
    o.x = a.x + b.x + c.x + d.x;
    o.y = a.y + b.y + c.y + d.y;
    o.z = a.z + b.z + c.z + d.z;
    o.w = a.w + b.w + c.w + d.w;
    ((float4*)out)[i] = o;
}

// ---------------------------------------------------------------------------
extern "C" void kernel_launch(void* const* d_in, const int* in_sizes, int n_in,
                              void* d_out, int out_size)
{
    (void)in_sizes; (void)n_in; (void)out_size;
    const float* x  = (const float*)d_in[0];
    const float* Gs = (const float*)d_in[1];
    const float* GA = (const float*)d_in[2];
    const float* GB = (const float*)d_in[3];
    const float* Us = (const float*)d_in[4];
    const float* UA = (const float*)d_in[5];
    const float* UB = (const float*)d_in[6];
    const float* Ds = (const float*)d_in[7];
    const float* DA = (const float*)d_in[8];
    const float* DB = (const float*)d_in[9];
    float* out = (float*)d_out;

    __half *wg, *wu, *wd;
    cudaGetSymbolAddress((void**)&wg, g_Wg);
    cudaGetSymbolAddress((void**)&wu, g_Wu);
    cudaGetSymbolAddress((void**)&wd, g_Wd);

    cudaFuncSetAttribute(k_dequant,     cudaFuncAttributeMaxDynamicSharedMemorySize, DQ_SMEM);
    cudaFuncSetAttribute(k_gemm_gateup, cudaFuncAttributeMaxDynamicSharedMemorySize, K2_SMEM);
    cudaFuncSetAttribute(k_gemm_down,   cudaFuncAttributeMaxDynamicSharedMemorySize, K3_SMEM);

    k_dequant<<<dim3(DM / 128, DF / 128), 256, DQ_SMEM>>>(Gs, GA, GB, wg, DM);
    k_dequant<<<dim3(DM / 128, DF / 128), 256, DQ_SMEM>>>(Us, UA, UB, wu, DM);
    k_dequant<<<dim3(DF / 128, DM / 128), 256, DQ_SMEM>>>(Ds, DA, DB, wd, DF);
    k_xt<<<dim3(DM / 32, SL / 32), 256>>>(x);

    k_gemm_gateup<<<dim3(SL / 128, DF / 128), 256, K2_SMEM>>>();
    k_gemm_down<<<dim3(SL / 128, DM / 128, 4), 256, K3_SMEM>>>();
    k_reduce<<<DM * SL / 4 / 256, 256>>>(out);
}

// round 9
// speedup vs baseline: 9.6713x; 1.0426x over previous
#include <cuda_runtime.h>
#include <cuda_fp16.h>
#include <cstdint>

#define DM 2048   // D_MODEL
#define DF 8192   // D_FF
#define RK 32     // RANK
#define SL 512    // S

// ---------------------------------------------------------------------------
// Global scratch
// ---------------------------------------------------------------------------
__device__ __half g_Wg[DF * DM];      // gate_eff fp16
__device__ __half g_Wu[DF * DM];      // up_eff fp16
__device__ __half g_Wd[DM * DF];      // down_eff fp16
__device__ __half g_xT[SL * DM];      // x transposed [s][c] fp16
__device__ __half g_mlpT[SL * DF];    // silu(g)*u transposed [s][ff] fp16
__device__ float  g_part[2 * DM * SL];// split-K=2 partials (fp32)

// ---------------------------------------------------------------------------
// Helpers
// ---------------------------------------------------------------------------
__device__ __forceinline__ float to_tf32(float x) {
    uint32_t u;
    asm("cvt.rna.tf32.f32 %0, %1;" : "=r"(u) : "f"(x));
    return __uint_as_float(u);
}
__device__ __forceinline__ uint32_t smem_u32(const void* p) {
    uint32_t a;
    asm("{ .reg .u64 t; cvta.to.shared.u64 t, %1; cvt.u32.u64 %0, t; }" : "=r"(a) : "l"(p));
    return a;
}
__device__ __forceinline__ void cp16(uint32_t dst, const void* src) {
    asm volatile("cp.async.cg.shared.global [%0], [%1], 16;" :: "r"(dst), "l"(src));
}
__device__ __forceinline__ void cp_commit() { asm volatile("cp.async.commit_group;"); }
__device__ __forceinline__ void cp_wait1()  { asm volatile("cp.async.wait_group 1;" ::: "memory"); }
__device__ __forceinline__ void cp_wait0()  { asm volatile("cp.async.wait_group 0;" ::: "memory"); }

// tf32 m16n8k8 (dequant scale GEMM)
__device__ __forceinline__ void mma8(float* c, const float* a, const float* b) {
    asm volatile(
        "mma.sync.aligned.m16n8k8.row.col.f32.tf32.tf32.f32 "
        "{%0,%1,%2,%3}, {%4,%5,%6,%7}, {%8,%9}, {%0,%1,%2,%3};"
        : "+f"(c[0]), "+f"(c[1]), "+f"(c[2]), "+f"(c[3])
        : "r"(__float_as_uint(a[0])), "r"(__float_as_uint(a[1])),
          "r"(__float_as_uint(a[2])), "r"(__float_as_uint(a[3])),
          "r"(__float_as_uint(b[0])), "r"(__float_as_uint(b[1])));
}
// fp16 m16n8k16 (main GEMMs), fp32 accum
__device__ __forceinline__ void mma16(float* c, const uint32_t* a, const uint32_t* b) {
    asm volatile(
        "mma.sync.aligned.m16n8k16.row.col.f32.f16.f16.f32 "
        "{%0,%1,%2,%3}, {%4,%5,%6,%7}, {%8,%9}, {%0,%1,%2,%3};"
        : "+f"(c[0]), "+f"(c[1]), "+f"(c[2]), "+f"(c[3])
        : "r"(a[0]), "r"(a[1]), "r"(a[2]), "r"(a[3]), "r"(b[0]), "r"(b[1]));
}
__device__ __forceinline__ void ldsm4(uint32_t* r, uint32_t addr) {
    asm volatile("ldmatrix.sync.aligned.m8n8.x4.shared.b16 {%0,%1,%2,%3}, [%4];"
                 : "=r"(r[0]), "=r"(r[1]), "=r"(r[2]), "=r"(r[3]) : "r"(addr));
}

// BK=64 tile: 128 rows x 64 k-halves padded to 72 (row stride 144 B, conflict-free ldmatrix)
#define PADH 72
#define TILE_H (128 * PADH * 2)    // 18432 B

// ---------------------------------------------------------------------------
// Kernel 1: merged dequant for all 3 matrices.
// grid = (1024, 1, 3): z selects {gate, up, down}; 1024 blocks tile the matrix.
// ---------------------------------------------------------------------------
#define DQ_SMEM 67584

__global__ __launch_bounds__(256, 1) void k_dequant(
    const float* __restrict__ Gs, const float* __restrict__ GA, const float* __restrict__ GB,
    const float* __restrict__ Us, const float* __restrict__ UA, const float* __restrict__ UB,
    const float* __restrict__ Ds, const float* __restrict__ DA, const float* __restrict__ DB)
{
    extern __shared__ float dsm[];
    float* sA = dsm;                    // [128][36] rows=f, cols=rank
    float* sB = dsm + 128 * 36;         // [128][36] rows=c, cols=rank (B transposed)
    int tid = threadIdx.x, wid = tid >> 5, lane = tid & 31;
    int g = lane >> 2, tg = lane & 3;
    int wm = wid & 3, wn = wid >> 2;

    const float *Ws, *Aa, *Bb;
    __half* Wo;
    int cols, cb, fb;
    if (blockIdx.z == 0) {
        Ws = Gs; Aa = GA; Bb = GB; Wo = g_Wg; cols = DM;
        cb = (blockIdx.x & 15) * 128; fb = (blockIdx.x >> 4) * 128;
    } else if (blockIdx.z == 1) {
        Ws = Us; Aa = UA; Bb = UB; Wo = g_Wu; cols = DM;
        cb = (blockIdx.x & 15) * 128; fb = (blockIdx.x >> 4) * 128;
    } else {
        Ws = Ds; Aa = DA; Bb = DB; Wo = g_Wd; cols = DF;
        cb = (blockIdx.x & 63) * 128; fb = (blockIdx.x >> 6) * 128;
    }

    #pragma unroll
    for (int t = 0; t < 16; t++) {
        int idx = tid + t * 256;
        int r = idx >> 5, k = idx & 31;
        sA[r * 36 + k] = to_tf32(Aa[(fb + r) * RK + k]);
        int rr = idx >> 7, c = idx & 127;
        sB[c * 36 + rr] = to_tf32(Bb[rr * cols + cb + c]);
    }
    __syncthreads();

    float acc[2][8][4];
    #pragma unroll
    for (int mt = 0; mt < 2; mt++)
        #pragma unroll
        for (int nt = 0; nt < 8; nt++)
            #pragma unroll
            for (int i = 0; i < 4; i++) acc[mt][nt][i] = 0.f;

    #pragma unroll
    for (int ks = 0; ks < 4; ks++) {
        int k0 = ks * 8;
        float bq[8][2];
        #pragma unroll
        for (int nt = 0; nt < 8; nt++) {
            const float* bp = sB + (wn * 64 + nt * 8 + g) * 36 + k0 + tg;
            bq[nt][0] = bp[0]; bq[nt][1] = bp[4];
        }
        #pragma unroll
        for (int mt = 0; mt < 2; mt++) {
            const float* ap = sA + (wm * 32 + mt * 16 + g) * 36 + k0 + tg;
            float a[4] = { ap[0], ap[8 * 36], ap[4], ap[8 * 36 + 4] };
            #pragma unroll
            for (int nt = 0; nt < 8; nt++) mma8(acc[mt][nt], a, bq[nt]);
        }
    }
    __syncthreads();

    float* sS = dsm;   // [128][132]
    #pragma unroll
    for (int mt = 0; mt < 2; mt++)
        #pragma unroll
        for (int nt = 0; nt < 8; nt++) {
            int r0 = wm * 32 + mt * 16 + g;
            int c0 = wn * 64 + nt * 8 + 2 * tg;
            #pragma unroll
            for (int i = 0; i < 4; i++)
                sS[(r0 + (i >> 1) * 8) * 132 + c0 + (i & 1)] = acc[mt][nt][i];
        }
    __syncthreads();

    #pragma unroll
    for (int t = 0; t < 16; t++) {
        int idx = tid + t * 256;
        int r = idx >> 5, c4 = idx & 31;
        const float4 w = *(const float4*)&Ws[(fb + r) * cols + cb + c4 * 4];
        const float4 s = *(const float4*)&sS[r * 132 + c4 * 4];
        __half2 lo = __floats2half2_rn(w.x * s.x, w.y * s.y);
        __half2 hi = __floats2half2_rn(w.z * s.z, w.w * s.w);
        uint2 o = { *(uint32_t*)&lo, *(uint32_t*)&hi };
        *(uint2*)&Wo[(fb + r) * cols + cb + c4 * 4] = o;
    }
}

// ---------------------------------------------------------------------------
// x transpose -> fp16
// ---------------------------------------------------------------------------
__global__ __launch_bounds__(256, 4) void k_xt(const float* __restrict__ x)
{
    __shared__ float sm[32][33];
    int tid = threadIdx.x, tx = tid & 31, ty = tid >> 5;
    int cb = blockIdx.x * 32, sb = blockIdx.y * 32;
    #pragma unroll
    for (int i = 0; i < 4; i++)
        sm[ty + i * 8][tx] = x[(cb + ty + i * 8) * SL + sb + tx];
    __syncthreads();
    #pragma unroll
    for (int i = 0; i < 4; i++)
        g_xT[(sb + ty + i * 8) * DM + cb + tx] = __float2half_rn(sm[tx][ty + i * 8]);
}

// ---------------------------------------------------------------------------
// Stage loader: 128 rows x 64 k-halves -> [row][PADH]; 4 cp16 per thread
// ---------------------------------------------------------------------------
__device__ __forceinline__ void load_tile64(uint32_t dst, const __half* __restrict__ src,
                                            int row_base, int ld, int c0, int tid)
{
    #pragma unroll
    for (int t = 0; t < 4; t++) {
        int id = tid + t * 256;
        int r = id >> 3, cbk = id & 7;
        cp16(dst + (r * PADH + cbk * 8) * 2, src + (row_base + r) * ld + c0 + cbk * 8);
    }
}

// ldmatrix per-lane byte offsets
__device__ __forceinline__ uint32_t a_off(int lane, int row_base) {
    return (uint32_t)((row_base + (lane & 15)) * (PADH * 2) + ((lane >> 4) * 16));
}
__device__ __forceinline__ uint32_t b_off(int lane, int row_base) {
    return (uint32_t)((row_base + ((lane >> 4) * 8) + (lane & 7)) * (PADH * 2) +
                      (((lane >> 3) & 1) * 16));
}

// ---------------------------------------------------------------------------
// Kernel 2: gate+up fp16 GEMM + SwiGLU -> g_mlpT (fp16)
// CTA: 128 f x 128 s, BK=64, 32 iters, 3-stage pipeline, 1 sync/iter.
// SMEM: 3 stages x (Ag|Au|Bx = 55296 B) = 165888 B.
// ---------------------------------------------------------------------------
#define K2_STG (3 * TILE_H)
#define K2_SMEM (3 * K2_STG)

__global__ __launch_bounds__(256, 1) void k_gemm_gateup()
{
    extern __shared__ char smemc[];
    __half* smh = (__half*)smemc;
    const uint32_t su = smem_u32(smemc);
    const int tid = threadIdx.x, wid = tid >> 5, lane = tid & 31;
    const int g = lane >> 2, tg = lane & 3;
    const int warp_m = wid & 3, warp_n = wid >> 2;
    const int sb = blockIdx.x * 128, fbase = blockIdx.y * 128;

    const uint32_t rA = a_off(lane, warp_m * 32);
    const uint32_t rB = b_off(lane, warp_n * 64);

    float accg[2][8][4], accu[2][8][4];
    #pragma unroll
    for (int mt = 0; mt < 2; mt++)
        #pragma unroll
        for (int nt = 0; nt < 8; nt++)
            #pragma unroll
            for (int i = 0; i < 4; i++) { accg[mt][nt][i] = 0.f; accu[mt][nt][i] = 0.f; }

    // prologue: stages 0 and 1
    #pragma unroll
    for (int p = 0; p < 2; p++) {
        uint32_t b = su + p * K2_STG;
        load_tile64(b,              g_Wg, fbase, DM, p * 64, tid);
        load_tile64(b + TILE_H,     g_Wu, fbase, DM, p * 64, tid);
        load_tile64(b + 2 * TILE_H, g_xT, sb,    DM, p * 64, tid);
        cp_commit();
    }

    int stg = 0;
    for (int i = 0; i < 32; i++) {
        if (i == 31) cp_wait0(); else cp_wait1();
        __syncthreads();                 // stage i ready; prior-iter reads done
        if (i < 30) {
            int ns = stg;                // (i+2)%3 == (i-1)%3 == slot being retired... compute below
            ns = stg + 2; if (ns >= 3) ns -= 3;
            uint32_t b = su + ns * K2_STG;
            int c0 = (i + 2) * 64;
            load_tile64(b,              g_Wg, fbase, DM, c0, tid);
            load_tile64(b + TILE_H,     g_Wu, fbase, DM, c0, tid);
            load_tile64(b + 2 * TILE_H, g_xT, sb,    DM, c0, tid);
            cp_commit();
        }

        const uint32_t bAg = su + stg * K2_STG;
        const uint32_t bAu = bAg + TILE_H;
        const uint32_t bBx = bAg + 2 * TILE_H;

        #pragma unroll
        for (int ks = 0; ks < 4; ks++) {
            const uint32_t kb = ks * 32;
            uint32_t bq[4][4];
            #pragma unroll
            for (int p = 0; p < 4; p++)
                ldsm4(bq[p], bBx + rB + p * 2304 + kb);
            #pragma unroll
            for (int mt = 0; mt < 2; mt++) {
                uint32_t ag[4], au[4];
                ldsm4(ag, bAg + rA + mt * 2304 + kb);
                ldsm4(au, bAu + rA + mt * 2304 + kb);
                #pragma unroll
                for (int p = 0; p < 4; p++) {
                    mma16(accg[mt][2 * p],     ag, &bq[p][0]);
                    mma16(accg[mt][2 * p + 1], ag, &bq[p][2]);
                    mma16(accu[mt][2 * p],     au, &bq[p][0]);
                    mma16(accu[mt][2 * p + 1], au, &bq[p][2]);
                }
            }
        }
        if (++stg == 3) stg = 0;
    }
    __syncthreads();   // mainloop reads done before smem reuse

    // epilogue: SwiGLU, transpose via smem (half), coalesced write
    __half* so = smh;   // [s 128][f pad 136] halves = 34816 B
    #pragma unroll
    for (int mt = 0; mt < 2; mt++)
        #pragma unroll
        for (int nt = 0; nt < 8; nt++) {
            int r0 = warp_m * 32 + mt * 16 + g;
            int c0 = warp_n * 64 + nt * 8 + 2 * tg;
            #pragma unroll
            for (int i = 0; i < 4; i++) {
                float gg = accg[mt][nt][i], uu = accu[mt][nt][i];
                float m = (gg / (1.f + __expf(-gg))) * uu;
                so[(c0 + (i & 1)) * 136 + r0 + (i >> 1) * 8] = __float2half_rn(m);
            }
        }
    __syncthreads();
    #pragma unroll
    for (int t = 0; t < 32; t++) {
        int idx = tid + t * 256;
        int s = idx >> 6, f2 = idx & 63;
        uint32_t v = *(const uint32_t*)&so[s * 136 + f2 * 2];
        *(uint32_t*)&g_mlpT[(sb + s) * DF + fbase + f2 * 2] = v;
    }
}

// ---------------------------------------------------------------------------
// Kernel 3: down fp16 GEMM, split-K=2 -> g_part.  CTA: 128 m x 128 s, BK=64.
// grid (4, 16, 2) = 128 CTAs -> single wave.  64 iters, 3-stage pipeline.
// SMEM: 3 stages x (Ad|Bm = 36864 B) = 110592 B.
// ---------------------------------------------------------------------------
#define K3_STG (2 * TILE_H)
#define K3_SMEM (3 * K3_STG)

__global__ __launch_bounds__(256, 1) void k_gemm_down()
{
    extern __shared__ char smemc[];
    const uint32_t su = smem_u32(smemc);
    const int tid = threadIdx.x, wid = tid >> 5, lane = tid & 31;
    const int g = lane >> 2, tg = lane & 3;
    const int warp_m = wid & 3, warp_n = wid >> 2;
    const int sb = blockIdx.x * 128, mbase = blockIdx.y * 128;
    const int kbase = blockIdx.z * 4096;

    const uint32_t rA = a_off(lane, warp_m * 32);
    const uint32_t rB = b_off(lane, warp_n * 64);

    float acc[2][8][4];
    #pragma unroll
    for (int mt = 0; mt < 2; mt++)
        #pragma unroll
        for (int nt = 0; nt < 8; nt++)
            #pragma unroll
            for (int i = 0; i < 4; i++) acc[mt][nt][i] = 0.f;

    #pragma unroll
    for (int p = 0; p < 2; p++) {
        uint32_t b = su + p * K3_STG;
        load_tile64(b,          g_Wd,   mbase, DF, kbase + p * 64, tid);
        load_tile64(b + TILE_H, g_mlpT, sb,    DF, kbase + p * 64, tid);
        cp_commit();
    }

    int stg = 0;
    for (int i = 0; i < 64; i++) {
        if (i == 63) cp_wait0(); else cp_wait1();
        __syncthreads();
        if (i < 62) {
            int ns = stg + 2; if (ns >= 3) ns -= 3;
            uint32_t b = su + ns * K3_STG;
            int c0 = kbase + (i + 2) * 64;
            load_tile64(b,          g_Wd,   mbase, DF, c0, tid);
            load_tile64(b + TILE_H, g_mlpT, sb,    DF, c0, tid);
            cp_commit();
        }

        const uint32_t bAd = su + stg * K3_STG;
        const uint32_t bBm = bAd + TILE_H;

        #pragma unroll
        for (int ks = 0; ks < 4; ks++) {
            const uint32_t kb = ks * 32;
            uint32_t bq[4][4];
            #pragma unroll
            for (int p = 0; p < 4; p++)
                ldsm4(bq[p], bBm + rB + p * 2304 + kb);
            #pragma unroll
            for (int mt = 0; mt < 2; mt++) {
                uint32_t a[4];
                ldsm4(a, bAd + rA + mt * 2304 + kb);
                #pragma unroll
                for (int p = 0; p < 4; p++) {
                    mma16(acc[mt][2 * p],     a, &bq[p][0]);
                    mma16(acc[mt][2 * p + 1], a, &bq[p][2]);
                }
            }
        }
        if (++stg == 3) stg = 0;
    }
    __syncthreads();

    // epilogue: stage [m][s] in smem (fp32), coalesced float4 partial writes
    float* so = (float*)smemc;   // [128][132] = 67584 B < K3_SMEM
    #pragma unroll
    for (int mt = 0; mt < 2; mt++)
        #pragma unroll
        for (int nt = 0; nt < 8; nt++) {
            int r0 = warp_m * 32 + mt * 16 + g;
            int c0 = warp_n * 64 + nt * 8 + 2 * tg;
            #pragma unroll
            for (int i = 0; i < 4; i++)
                so[(r0 + (i >> 1) * 8) * 132 + c0 + (i & 1)] = acc[mt][nt][i];
        }
    __syncthreads();
    #pragma unroll
    for (int t = 0; t < 16; t++) {
        int idx = tid + t * 256;
        int m = idx >> 5, c4 = idx & 31;
        float4 v = *(const float4*)&so[m * 132 + c4 * 4];
        *(float4*)&g_part[(blockIdx.z * DM + mbase + m) * SL + sb + c4 * 4] = v;
    }
}

// ---------------------------------------------------------------------------
// Kernel 4: split-K reduce (K=2)
// ---------------------------------------------------------------------------
__global__ __launch_bounds__(256, 4) void k_reduce(float* __restrict__ out)
{
    int i = blockIdx.x * 256 + threadIdx.x;
    const float4* p = (const float4*)g_part;
    const int n4 = DM * SL / 4;
    float4 a = p[i], b = p[i + n4];
    float4 o;
    o.x = a.x + b.x; o.y = a.y + b.y; o.z = a.z + b.z; o.w = a.w + b.w;
    ((float4*)out)[i] = o;
}

// ---------------------------------------------------------------------------
extern "C" void kernel_launch(void* const* d_in, const int* in_sizes, int n_in,
                              void* d_out, int out_size)
{
    (void)in_sizes; (void)n_in; (void)out_size;
    const float* x  = (const float*)d_in[0];
    const float* Gs = (const float*)d_in[1];
    const float* GA = (const float*)d_in[2];
    const float* GB = (const float*)d_in[3];
    const float* Us = (const float*)d_in[4];
    const float* UA = (const float*)d_in[5];
    const float* UB = (const float*)d_in[6];
    const float* Ds = (const float*)d_in[7];
    const float* DA = (const float*)d_in[8];
    const float* DB = (const float*)d_in[9];
    float* out = (float*)d_out;

    cudaFuncSetAttribute(k_dequant,     cudaFuncAttributeMaxDynamicSharedMemorySize, DQ_SMEM);
    cudaFuncSetAttribute(k_gemm_gateup, cudaFuncAttributeMaxDynamicSharedMemorySize, K2_SMEM);
    cudaFuncSetAttribute(k_gemm_down,   cudaFuncAttributeMaxDynamicSharedMemorySize, K3_SMEM);

    k_dequant<<<dim3(1024, 1, 3), 256, DQ_SMEM>>>(Gs, GA, GB, Us, UA, UB, Ds, DA, DB);
    k_xt<<<dim3(DM / 32, SL / 32), 256>>>(x);

    k_gemm_gateup<<<dim3(SL / 128, DF / 128), 256, K2_SMEM>>>();
    k_gemm_down<<<dim3(SL / 128, DM / 128, 2), 256, K3_SMEM>>>();
    k_reduce<<<DM * SL / 4 / 256, 256>>>(out);
}